// round 1
// baseline (speedup 1.0000x reference)
#include <cuda_runtime.h>
#include <stdint.h>

// Problem constants (fixed by the dataset problem)
#define BATCH 4096
#define IN_F  2048
#define OUT_F 4096
#define WORDS (IN_F / 64)   // 32 x u64 per row

// Scratch (allocation-free: __device__ globals)
__device__ uint64_t g_xbits[(size_t)BATCH * WORDS];
__device__ uint64_t g_pbits[(size_t)OUT_F * WORDS];
__device__ uint64_t g_xsig[BATCH];
__device__ uint64_t g_psig[OUT_F];

// -----------------------------------------------------------------------------
// Pack kernel: one warp per row. First BATCH warps pack x rows, next OUT_F warps
// compute the BSGen path bit from the weight and pack it.
// Per-row 64-bit signature = multiplicative mix of the 32 words.
// -----------------------------------------------------------------------------
__global__ void fsu_pack_kernel(const float* __restrict__ x,
                                const float* __restrict__ w,
                                const float* __restrict__ rng)
{
    const int gwarp = (blockIdx.x * blockDim.x + threadIdx.x) >> 5;
    const int lane  = threadIdx.x & 31;
    const bool isX  = gwarp < BATCH;
    const int row   = isX ? gwarp : (gwarp - BATCH);
    if (!isX && row >= OUT_F) return;

    const float rv = __ldg(rng);
    const float* src = isX ? (x + (size_t)row * IN_F)
                           : (w + (size_t)row * IN_F);

    uint64_t sig = 0;
    uint64_t myword = 0;
    uint32_t lo = 0;

    #pragma unroll 8
    for (int it = 0; it < IN_F / 32; ++it) {
        const float v = __ldg(src + it * 32 + lane);
        bool bit;
        if (isX) {
            bit = (v > 0.5f);                       // x is exactly 0.0 or 1.0
        } else {
            // BinGen/BSGen: prob=(w+1)*0.5; source=round(prob*2^WIDTH); bit = source > rng
            const float prob = (v + 1.0f) * 0.5f;
            const float s    = rintf(prob * 256.0f); // round-half-to-even == jnp.round
            bit = (s > rv);
        }
        const uint32_t b = __ballot_sync(0xFFFFFFFFu, bit);
        if ((it & 1) == 0) {
            lo = b;
        } else {
            const uint64_t word = (uint64_t)lo | ((uint64_t)b << 32);
            const int widx = it >> 1;               // which u64 word of the row
            if (lane == widx) myword = word;        // keep it for a coalesced store
            sig = sig * 0x9E3779B97F4A7C15ull + word; // identical on all lanes
        }
    }

    if (isX) {
        g_xbits[(size_t)row * WORDS + lane] = myword;
        if (lane == 0) g_xsig[row] = sig;
    } else {
        g_pbits[(size_t)row * WORDS + lane] = myword;
        if (lane == 0) g_psig[row] = sig;
    }
}

// Exact fallback: compare the full 2048-bit rows. Essentially never taken
// (64-bit signature collision), but guarantees bit-exact correctness.
__device__ __noinline__ float fsu_full_cmp(int b, int o)
{
    const uint64_t* xb = &g_xbits[(size_t)b * WORDS];
    const uint64_t* pb = &g_pbits[(size_t)o * WORDS];
    #pragma unroll 8
    for (int k = 0; k < WORDS; ++k) {
        if (__ldg(xb + k) != __ldg(pb + k)) return 0.0f;
    }
    return 1.0f;
}

// -----------------------------------------------------------------------------
// Output kernel: one block per batch row. out[b,o] = 1 iff rows bit-identical.
// Signature pre-filter, float4 stores (HBM write bound: 64 MB).
// -----------------------------------------------------------------------------
__global__ void fsu_out_kernel(float* __restrict__ out)
{
    const int b = blockIdx.x;
    const uint64_t xs = g_xsig[b];

    float4* outv = reinterpret_cast<float4*>(out + (size_t)b * OUT_F);

    #pragma unroll
    for (int j = 0; j < OUT_F / 4; j += 256) {
        const int idx = j + threadIdx.x;   // float4 index within the row
        const int o   = idx * 4;
        float4 r = make_float4(0.0f, 0.0f, 0.0f, 0.0f);
        // Sigs are 32 KB total, fully L1/L2-resident after the first warps.
        if (__ldg(&g_psig[o + 0]) == xs) r.x = fsu_full_cmp(b, o + 0);
        if (__ldg(&g_psig[o + 1]) == xs) r.y = fsu_full_cmp(b, o + 1);
        if (__ldg(&g_psig[o + 2]) == xs) r.z = fsu_full_cmp(b, o + 2);
        if (__ldg(&g_psig[o + 3]) == xs) r.w = fsu_full_cmp(b, o + 3);
        outv[idx] = r;
    }
}

extern "C" void kernel_launch(void* const* d_in, const int* in_sizes, int n_in,
                              void* d_out, int out_size)
{
    const float* x   = (const float*)d_in[0];
    const float* w   = (const float*)d_in[1];
    const float* rng = (const float*)d_in[2];
    float* out = (float*)d_out;

    // Pack: (BATCH + OUT_F) warps total
    const int totalWarps = BATCH + OUT_F;            // 8192
    const int threads = 256;                         // 8 warps/block
    const int blocks = (totalWarps * 32) / threads;  // 1024 blocks
    fsu_pack_kernel<<<blocks, threads>>>(x, w, rng);

    // Output: one block per batch row
    fsu_out_kernel<<<BATCH, 256>>>(out);
}